// round 4
// baseline (speedup 1.0000x reference)
#include <cuda_runtime.h>
#include <math.h>

#define BB 16
#define NN 4096
#define CC 256
#define KK 8
#define SLICES 8
#define EPSF 1e-6f
#define RATIOF 0.1f

#define BN (BB*NN)   /* 65536 tokens */
#define BK (BB*KK)   /* 128 (batch, expert) pairs */

// ---------------- device scratch (no allocations allowed) ----------------
__device__ float  g_gbias[BK];
__device__ int    g_route_e[BN];      // packed e0 | e1<<8
__device__ float2 g_route_w[BN];      // (w0, w1)
__device__ int    g_cnt[KK];
__device__ float  g_confpart[BN/8];
__device__ int    g_listcnt[BK];
__device__ float  g_mass[BK];
__device__ int    g_list_n[BK*NN];
__device__ float  g_list_w[BK*NN];
__device__ float  g_part[BK*SLICES*CC];

// ---------------- f32x2 packed-FMA helpers ----------------
__device__ __forceinline__ unsigned long long ffma2(unsigned long long a, unsigned long long b, unsigned long long c){
    unsigned long long d;
    asm("fma.rn.f32x2 %0, %1, %2, %3;" : "=l"(d) : "l"(a), "l"(b), "l"(c));
    return d;
}
__device__ __forceinline__ unsigned long long pack2(float x, float y){
    unsigned long long d; asm("mov.b64 %0, {%1,%2};" : "=l"(d) : "f"(x), "f"(y)); return d;
}
__device__ __forceinline__ void unpack2(unsigned long long v, float& lo, float& hi){
    asm("mov.b64 {%0,%1}, %2;" : "=f"(lo), "=f"(hi) : "l"(v));
}

// ---------------- K0: zero counters + per-(b,k) gate bias ----------------
__global__ void k0_init(const float* __restrict__ geno, const float* __restrict__ Wgg,
                        const float* __restrict__ bgg, const float* __restrict__ bg){
    int i = threadIdx.x;              // 0..127 == (b,k)
    if (i < KK) g_cnt[i] = 0;
    int b = i / KK, k = i % KK;
    const float* g = geno + b*CC;
    const float* w = Wgg + k*CC;
    float s = 0.f;
    #pragma unroll 8
    for (int j = 0; j < CC; j++) s += g[j]*w[j];
    g_gbias[i] = bg[k] + RATIOF*(s + bgg[k]);
}

// ---------------- K1: gating (1 warp per token) ----------------
__global__ void k1_gate(const float* __restrict__ tokens, const float* __restrict__ Wg){
    int warp = threadIdx.x >> 5, lane = threadIdx.x & 31;
    int idx = blockIdx.x*8 + warp;
    int b = idx >> 12;
    const float* x = tokens + (size_t)idx*CC;

    float acc[KK];
    #pragma unroll
    for (int k = 0; k < KK; k++) acc[k] = 0.f;
    #pragma unroll
    for (int i = 0; i < 8; i++){
        int j = lane + 32*i;
        float xv = x[j];
        #pragma unroll
        for (int k = 0; k < KK; k++) acc[k] = fmaf(xv, Wg[k*CC + j], acc[k]);
    }
    #pragma unroll
    for (int k = 0; k < KK; k++){
        #pragma unroll
        for (int off = 16; off; off >>= 1) acc[k] += __shfl_xor_sync(0xffffffffu, acc[k], off);
    }

    __shared__ int   s_cnt[KK];
    __shared__ float s_conf[8];
    if (threadIdx.x < KK) s_cnt[threadIdx.x] = 0;
    __syncthreads();

    if (lane == 0){
        float v0 = -1e30f, v1 = -1e30f; int i0 = 0, i1 = 0;
        #pragma unroll
        for (int k = 0; k < KK; k++){
            float v = acc[k] + g_gbias[b*KK + k];
            if (v > v0){ v1 = v0; i1 = i0; v0 = v; i0 = k; }
            else if (v > v1){ v1 = v; i1 = k; }
        }
        float e  = expf(v1 - v0);
        float w0 = 1.f/(1.f + e);
        float w1 = e/(1.f + e);
        w0 = fmaxf(w0, EPSF); w1 = fmaxf(w1, EPSF);
        float inv = 1.f/(w0 + w1); w0 *= inv; w1 *= inv;
        g_route_e[idx] = i0 | (i1 << 8);
        g_route_w[idx] = make_float2(w0, w1);
        atomicAdd(&s_cnt[i0], 1);
        atomicAdd(&s_cnt[i1], 1);
        s_conf[warp] = v0 - v1;
    }
    __syncthreads();
    if (threadIdx.x < KK) atomicAdd(&g_cnt[threadIdx.x], s_cnt[threadIdx.x]);
    if (threadIdx.x == 0){
        float c = 0.f;
        #pragma unroll
        for (int w = 0; w < 8; w++) c += s_conf[w];
        g_confpart[blockIdx.x] = c;
    }
}

// ---------------- K2: deterministic compaction per (b,k) ----------------
__global__ void k2_compact(){
    int bk = blockIdx.x, b = bk >> 3, k = bk & 7;
    int tid = threadIdx.x, lane = tid & 31, warp = tid >> 5;
    __shared__ int   s_base, s_wtot[8], s_woff[8];
    __shared__ float s_wsum[8];
    __shared__ float s_mass;
    if (tid == 0){ s_base = 0; s_mass = 0.f; }
    __syncthreads();

    for (int r = 0; r < 16; r++){
        int t   = r*256 + tid;
        int idx = b*NN + t;
        int pe  = g_route_e[idx];
        float2 ww = g_route_w[idx];
        int e0 = pe & 255, e1 = pe >> 8;
        float myw = (e0 == k) ? ww.x : ((e1 == k) ? ww.y : 0.f);
        int pres = (e0 == k) || (e1 == k);

        unsigned ball = __ballot_sync(0xffffffffu, pres);
        int rank = __popc(ball & ((1u << lane) - 1u));
        // deterministic warp-reduce of weights (fixed butterfly tree)
        float wsum = myw;
        #pragma unroll
        for (int off = 16; off; off >>= 1) wsum += __shfl_xor_sync(0xffffffffu, wsum, off);
        if (lane == 0){ s_wtot[warp] = __popc(ball); s_wsum[warp] = wsum; }
        __syncthreads();
        if (tid == 0){
            int o = s_base; float ms = s_mass;
            #pragma unroll
            for (int w = 0; w < 8; w++){ s_woff[w] = o; o += s_wtot[w]; ms += s_wsum[w]; }
            s_base = o; s_mass = ms;
        }
        __syncthreads();
        if (pres){
            int pos = s_woff[warp] + rank;
            g_list_n[bk*NN + pos] = t;
            g_list_w[bk*NN + pos] = myw;
        }
        __syncthreads();
    }
    if (tid == 0){ g_listcnt[bk] = s_base; g_mass[bk] = s_mass; }
}

// ---------------- K3: layer-1 GEMM + relu + weighted reduce ----------------
// W1-resident: each block owns a 128-out-channel half of W1[k] in smem
// (loaded once), streams 64-token X chunks through, software-pipelined in
// two j-halves (X0 = j 0..127, X1 = j 128..255) so LDG overlaps compute.
// smem words: X0[128j][64t] | X1[128j][64t] | Ws[128c][260] | Wl[2][64]
#define WSTRIDE      260
#define X_HALF_WORDS (128*64)            /* 8192 */
#define XS_WORDS     (2*X_HALF_WORDS)    /* 16384 */
#define WS_OFF       XS_WORDS
#define WS_WORDS     (128*WSTRIDE)       /* 33280 */
#define WL_OFF       (WS_OFF + WS_WORDS)
#define SM_WORDS     (WL_OFF + 128)      /* 49792 words = 199168 B */

__global__ void __launch_bounds__(256, 1)
k3_gemm(const float* __restrict__ tokens, const float* __restrict__ W1, const float* __restrict__ b1){
    extern __shared__ float sm[];
    float* Ws = sm + WS_OFF;
    float* Wl = sm + WL_OFF;   // [2][64] double-buffered by chunk parity

    // blockIdx.x = bk * (2*SLICES) + half*SLICES + sl
    int bk   = blockIdx.x / (2*SLICES);
    int rest = blockIdx.x % (2*SLICES);
    int half = rest / SLICES;
    int sl   = rest % SLICES;
    int b = bk >> 3, k = bk & 7;

    int cnt = g_listcnt[bk];
    int per = (cnt + SLICES - 1) / SLICES;
    int start = sl*per;
    int end   = start + per; if (end > cnt) end = cnt;

    int tid = threadIdx.x;
    int a = tid & 31, bb = tid >> 5;    // compute: 32 channel lanes x 8 warps(token groups)
    int tt = tid & 63, q = tid >> 6;    // X load: 64 tokens x 4 quarters (q covers 32 j per half)

    if (start >= end){                  // idle slice: write zeros, skip W load
        if (tid < 128) g_part[(size_t)(bk*SLICES + sl)*CC + half*128 + tid] = 0.f;
        return;
    }

    // ---- load W1 half [128c][256j] into smem once (row stride 260) ----
    {
        int r = tid >> 1, p = tid & 1;  // 128 rows x 2 half-rows
        const float4* wr = (const float4*)(W1 + ((size_t)k*CC + half*128 + r)*CC + p*128);
        float* dst = Ws + r*WSTRIDE + p*128;
        #pragma unroll
        for (int i = 0; i < 32; i++){
            float4 v = wr[i];
            dst[i*4+0] = v.x; dst[i*4+1] = v.y; dst[i*4+2] = v.z; dst[i*4+3] = v.w;
        }
    }

    float bias[4];
    #pragma unroll
    for (int m = 0; m < 4; m++) bias[m] = b1[k*CC + half*128 + m*32 + a];

    float cpart[4];
    #pragma unroll
    for (int m = 0; m < 4; m++) cpart[m] = 0.f;

    // ---- prologue: fetch chunk0 half0 into registers ----
    float4 xreg[8];
    float  wlreg;
    const float* xbase;            // token row base for current chunk (this thread's tt)
    {
        int tg = start + tt;
        int valid = tg < end;
        int n = g_list_n[bk*NN + (valid ? tg : start)];
        wlreg = valid ? g_list_w[bk*NN + tg] : 0.f;
        xbase = tokens + (size_t)(b*NN + n)*CC;
        const float4* xr = (const float4*)(xbase + q*32);      // half0: j = q*32 + i*4
        #pragma unroll
        for (int i = 0; i < 8; i++) xreg[i] = xr[i];
    }

    int parity = 0;
    for (int t0 = start; t0 < end; t0 += 64, parity ^= 1){
        // ---- STS half0 + Wl ----
        {
            float* X0 = sm;
            #pragma unroll
            for (int i = 0; i < 8; i++){
                int j = q*32 + i*4;
                X0[(j+0)*64 + tt] = xreg[i].x;
                X0[(j+1)*64 + tt] = xreg[i].y;
                X0[(j+2)*64 + tt] = xreg[i].z;
                X0[(j+3)*64 + tt] = xreg[i].w;
            }
            if (q == 0) Wl[parity*64 + tt] = wlreg;
        }
        __syncthreads();                       // sync1: X0/Wl ready

        // ---- LDG half1 of this chunk (overlaps half0 compute) ----
        {
            const float4* xr = (const float4*)(xbase + 128 + q*32);
            #pragma unroll
            for (int i = 0; i < 8; i++) xreg[i] = xr[i];
        }

        unsigned long long acc[4][4];
        #pragma unroll
        for (int m = 0; m < 4; m++)
            #pragma unroll
            for (int p = 0; p < 4; p++) acc[m][p] = 0ull;

        // ---- compute half0: j = 0..127 ----
        {
            const float* Xh = sm;
            for (int j0 = 0; j0 < 128; j0 += 4){
                ulonglong2 xa[4], xb[4];
                #pragma unroll
                for (int u = 0; u < 4; u++){
                    const ulonglong2* xp = (const ulonglong2*)(Xh + (j0 + u)*64 + bb*8);
                    xa[u] = xp[0];
                    xb[u] = xp[1];
                }
                #pragma unroll
                for (int m = 0; m < 4; m++){
                    float4 wv = *(const float4*)(Ws + (m*32 + a)*WSTRIDE + j0);  // LDS.128, conflict-free
                    unsigned long long w0 = pack2(wv.x, wv.x);
                    unsigned long long w1 = pack2(wv.y, wv.y);
                    unsigned long long w2 = pack2(wv.z, wv.z);
                    unsigned long long w3 = pack2(wv.w, wv.w);
                    acc[m][0] = ffma2(w0, xa[0].x, acc[m][0]);
                    acc[m][1] = ffma2(w0, xa[0].y, acc[m][1]);
                    acc[m][2] = ffma2(w0, xb[0].x, acc[m][2]);
                    acc[m][3] = ffma2(w0, xb[0].y, acc[m][3]);
                    acc[m][0] = ffma2(w1, xa[1].x, acc[m][0]);
                    acc[m][1] = ffma2(w1, xa[1].y, acc[m][1]);
                    acc[m][2] = ffma2(w1, xb[1].x, acc[m][2]);
                    acc[m][3] = ffma2(w1, xb[1].y, acc[m][3]);
                    acc[m][0] = ffma2(w2, xa[2].x, acc[m][0]);
                    acc[m][1] = ffma2(w2, xa[2].y, acc[m][1]);
                    acc[m][2] = ffma2(w2, xb[2].x, acc[m][2]);
                    acc[m][3] = ffma2(w2, xb[2].y, acc[m][3]);
                    acc[m][0] = ffma2(w3, xa[3].x, acc[m][0]);
                    acc[m][1] = ffma2(w3, xa[3].y, acc[m][1]);
                    acc[m][2] = ffma2(w3, xb[3].x, acc[m][2]);
                    acc[m][3] = ffma2(w3, xb[3].y, acc[m][3]);
                }
            }
        }

        // ---- STS half1 ----
        {
            float* X1 = sm + X_HALF_WORDS;
            #pragma unroll
            for (int i = 0; i < 8; i++){
                int j = q*32 + i*4;
                X1[(j+0)*64 + tt] = xreg[i].x;
                X1[(j+1)*64 + tt] = xreg[i].y;
                X1[(j+2)*64 + tt] = xreg[i].z;
                X1[(j+3)*64 + tt] = xreg[i].w;
            }
        }
        __syncthreads();                       // sync2: X1 ready, X0 free

        // ---- LDG half0 of NEXT chunk (overlaps half1 compute) ----
        float wl_next = 0.f;
        if (t0 + 64 < end){
            int tg = t0 + 64 + tt;
            int valid = tg < end;
            int n = g_list_n[bk*NN + (valid ? tg : (t0 + 64))];
            wl_next = valid ? g_list_w[bk*NN + tg] : 0.f;
            xbase = tokens + (size_t)(b*NN + n)*CC;
            const float4* xr = (const float4*)(xbase + q*32);
            #pragma unroll
            for (int i = 0; i < 8; i++) xreg[i] = xr[i];
        }

        // ---- compute half1: j = 128..255 ----
        {
            const float* Xh = sm + X_HALF_WORDS;
            for (int j0 = 0; j0 < 128; j0 += 4){
                ulonglong2 xa[4], xb[4];
                #pragma unroll
                for (int u = 0; u < 4; u++){
                    const ulonglong2* xp = (const ulonglong2*)(Xh + (j0 + u)*64 + bb*8);
                    xa[u] = xp[0];
                    xb[u] = xp[1];
                }
                #pragma unroll
                for (int m = 0; m < 4; m++){
                    float4 wv = *(const float4*)(Ws + (m*32 + a)*WSTRIDE + 128 + j0);
                    unsigned long long w0 = pack2(wv.x, wv.x);
                    unsigned long long w1 = pack2(wv.y, wv.y);
                    unsigned long long w2 = pack2(wv.z, wv.z);
                    unsigned long long w3 = pack2(wv.w, wv.w);
                    acc[m][0] = ffma2(w0, xa[0].x, acc[m][0]);
                    acc[m][1] = ffma2(w0, xa[0].y, acc[m][1]);
                    acc[m][2] = ffma2(w0, xb[0].x, acc[m][2]);
                    acc[m][3] = ffma2(w0, xb[0].y, acc[m][3]);
                    acc[m][0] = ffma2(w1, xa[1].x, acc[m][0]);
                    acc[m][1] = ffma2(w1, xa[1].y, acc[m][1]);
                    acc[m][2] = ffma2(w1, xb[1].x, acc[m][2]);
                    acc[m][3] = ffma2(w1, xb[1].y, acc[m][3]);
                    acc[m][0] = ffma2(w2, xa[2].x, acc[m][0]);
                    acc[m][1] = ffma2(w2, xa[2].y, acc[m][1]);
                    acc[m][2] = ffma2(w2, xb[2].x, acc[m][2]);
                    acc[m][3] = ffma2(w2, xb[2].y, acc[m][3]);
                    acc[m][0] = ffma2(w3, xa[3].x, acc[m][0]);
                    acc[m][1] = ffma2(w3, xa[3].y, acc[m][1]);
                    acc[m][2] = ffma2(w3, xb[3].x, acc[m][2]);
                    acc[m][3] = ffma2(w3, xb[3].y, acc[m][3]);
                }
            }
        }

        // ---- per-chunk epilogue: bias + relu + token-weighted accumulate ----
        #pragma unroll
        for (int m = 0; m < 4; m++){
            float s = 0.f;
            #pragma unroll
            for (int p = 0; p < 4; p++){
                float h0, h1; unpack2(acc[m][p], h0, h1);
                int t = bb*8 + 2*p;
                s += Wl[parity*64 + t]     * fmaxf(h0 + bias[m], 0.f);
                s += Wl[parity*64 + t + 1] * fmaxf(h1 + bias[m], 0.f);
            }
            cpart[m] += s;
        }
        wlreg = wl_next;
    }

    // block reduce across the 8 token groups (fixed order => deterministic)
    __syncthreads();
    #pragma unroll
    for (int m = 0; m < 4; m++) sm[(m*32 + a)*8 + bb] = cpart[m];
    __syncthreads();
    if (tid < 128){
        float s = 0.f;
        #pragma unroll
        for (int g = 0; g < 8; g++) s += sm[tid*8 + g];
        g_part[(size_t)(bk*SLICES + sl)*CC + half*128 + tid] = s;
    }
}

// ---------------- K4: slice reduce + layer-2 GEMM + division ----------------
__global__ void k4_layer2(const float* __restrict__ W2, const float* __restrict__ b2,
                          float* __restrict__ out){
    int bk = blockIdx.x, k = bk & 7;
    int c = threadIdx.x;
    __shared__ __align__(16) float Hs[CC];
    float h = 0.f;
    #pragma unroll
    for (int s = 0; s < SLICES; s++) h += g_part[(size_t)(bk*SLICES + s)*CC + c];
    Hs[c] = h;
    __syncthreads();
    float mass = g_mass[bk];
    float accv = b2[k*CC + c]*mass;
    const float4* w2r = (const float4*)(W2 + (size_t)(k*CC + c)*CC);
    const float4* hr  = (const float4*)Hs;
    #pragma unroll 8
    for (int j = 0; j < 64; j++){
        float4 w = w2r[j]; float4 hh = hr[j];
        accv += w.x*hh.x + w.y*hh.y + w.z*hh.z + w.w*hh.w;
    }
    out[(size_t)bk*CC + c] = accv / fmaxf(mass, EPSF);
}

// ---------------- K5: lb_loss + routing_confidence ----------------
__global__ void k5_final(float* __restrict__ out, int out_size){
    __shared__ float sr[256];
    int tid = threadIdx.x;
    float s = 0.f;
    #pragma unroll 4
    for (int i = 0; i < 32; i++) s += g_confpart[tid*32 + i];
    sr[tid] = s;
    __syncthreads();
    for (int s2 = 128; s2; s2 >>= 1){
        if (tid < s2) sr[tid] += sr[tid + s2];
        __syncthreads();
    }
    if (tid == 0){
        float conf = sr[0] / (float)BN;
        float u[KK]; float mean = 0.f;
        #pragma unroll
        for (int k = 0; k < KK; k++){ u[k] = (float)g_cnt[k] / (float)BN; mean += u[k]; }
        mean /= (float)KK;
        float var = 0.f;
        #pragma unroll
        for (int k = 0; k < KK; k++){ float d = u[k] - mean; var += d*d; }
        var /= (float)KK;
        float stdv = sqrtf(var);
        float ratio = stdv / (mean + EPSF);
        if (out_size > BB*KK*CC)     out[BB*KK*CC]     = ratio*ratio;
        if (out_size > BB*KK*CC + 1) out[BB*KK*CC + 1] = conf;
    }
}

// ---------------- launch ----------------
extern "C" void kernel_launch(void* const* d_in, const int* in_sizes, int n_in,
                              void* d_out, int out_size){
    const float* tokens = (const float*)d_in[0];
    const float* geno   = (const float*)d_in[1];
    const float* Wg     = (const float*)d_in[2];
    const float* bg     = (const float*)d_in[3];
    const float* Wgg    = (const float*)d_in[4];
    const float* bgg    = (const float*)d_in[5];
    const float* W1     = (const float*)d_in[6];
    const float* b1     = (const float*)d_in[7];
    const float* W2     = (const float*)d_in[8];
    const float* b2     = (const float*)d_in[9];
    float* out = (float*)d_out;

    // unconditional every call: deterministic, capture-safe (host attribute set)
    cudaFuncSetAttribute(k3_gemm, cudaFuncAttributeMaxDynamicSharedMemorySize, SM_WORDS*4);

    k0_init   <<<1, 128>>>(geno, Wgg, bgg, bg);
    k1_gate   <<<BN/8, 256>>>(tokens, Wg);
    k2_compact<<<BK, 256>>>();
    k3_gemm   <<<BK*2*SLICES, 256, SM_WORDS*4>>>(tokens, W1, b1);
    k4_layer2 <<<BK, 256>>>(W2, b2, out);
    k5_final  <<<1, 256>>>(out, out_size);
}